// round 1
// baseline (speedup 1.0000x reference)
#include <cuda_runtime.h>

#define Bn 8
#define Sn 1024
#define Dn 1024
#define Hn 16
#define HDn 64

// Scratch: Q, K, V in [B, H, S, HD] layout (33.5 MB each).
__device__ float g_q[Bn * Hn * Sn * HDn];
__device__ float g_k[Bn * Hn * Sn * HDn];
__device__ float g_v[Bn * Hn * Sn * HDn];

// ---------------------------------------------------------------------------
// SGEMM: out = A[8192x1024] @ W[1024x1024] + bias, scattered to [B,H,S,HD].
// BM=BN=128, BK=16, 256 threads, 8x8 per-thread microtile.
// sel: 0 -> g_q, 1 -> g_k, 2 -> g_v
// ---------------------------------------------------------------------------
__global__ __launch_bounds__(256) void qkv_gemm_kernel(
    const float* __restrict__ A, const float* __restrict__ W,
    const float* __restrict__ bias, int sel)
{
    constexpr int M = Bn * Sn;   // 8192
    constexpr int N = Dn;        // 1024
    constexpr int K = Dn;        // 1024
    constexpr int BM = 128, BN = 128, BK = 16, TM = 8, TN = 8;

    __shared__ float As[BK][BM];   // transposed A tile
    __shared__ float Bs[BK][BN];

    float* out = (sel == 0) ? g_q : (sel == 1) ? g_k : g_v;

    const int tid = threadIdx.x;
    const int blockRow = blockIdx.y * BM;
    const int blockCol = blockIdx.x * BN;

    const int threadRow = (tid / 16) * TM;   // 0..120
    const int threadCol = (tid % 16) * TN;   // 0..120

    float acc[TM][TN];
#pragma unroll
    for (int i = 0; i < TM; i++)
#pragma unroll
        for (int j = 0; j < TN; j++) acc[i][j] = 0.f;

    for (int k0 = 0; k0 < K; k0 += BK) {
        // Load A tile (128x16) and B tile (16x128), 2 float4 per thread each.
#pragma unroll
        for (int it = 0; it < 2; it++) {
            int lin = tid + it * 256;              // 0..511 float4 units
            int ra = lin >> 2;                     // 0..127
            int ca = (lin & 3) << 2;               // 0,4,8,12
            float4 av = *(const float4*)(A + (size_t)(blockRow + ra) * K + k0 + ca);
            As[ca + 0][ra] = av.x;
            As[ca + 1][ra] = av.y;
            As[ca + 2][ra] = av.z;
            As[ca + 3][ra] = av.w;

            int rb = lin >> 5;                     // 0..15
            int cb = (lin & 31) << 2;              // 0..124
            *(float4*)&Bs[rb][cb] =
                *(const float4*)(W + (size_t)(k0 + rb) * N + blockCol + cb);
        }
        __syncthreads();

#pragma unroll
        for (int kk = 0; kk < BK; kk++) {
            float regM[TM], regN[TN];
            *(float4*)&regM[0] = *(const float4*)&As[kk][threadRow];
            *(float4*)&regM[4] = *(const float4*)&As[kk][threadRow + 4];
            *(float4*)&regN[0] = *(const float4*)&Bs[kk][threadCol];
            *(float4*)&regN[4] = *(const float4*)&Bs[kk][threadCol + 4];
#pragma unroll
            for (int i = 0; i < TM; i++)
#pragma unroll
                for (int j = 0; j < TN; j++)
                    acc[i][j] += regM[i] * regN[j];
        }
        __syncthreads();
    }

    // Epilogue: add bias, scatter to [B,H,S,HD].
#pragma unroll
    for (int i = 0; i < TM; i++) {
        int m = blockRow + threadRow + i;
        int b = m >> 10;          // m / S
        int s = m & 1023;         // m % S
#pragma unroll
        for (int j = 0; j < TN; j++) {
            int n = blockCol + threadCol + j;
            int h = n >> 6;       // n / HD
            int hd = n & 63;      // n % HD
            out[(((size_t)(b * Hn + h) * Sn + s) * HDn) + hd] = acc[i][j] + bias[n];
        }
    }
}

// ---------------------------------------------------------------------------
// Flash-style attention: grid (S/64, B*H), 128 threads.
// Q tile = 64 rows, K/V tile = 32 keys per iteration, online softmax.
// Thread t: row r = t % 64, half = t / 64.
//   scores: cols [half*16, half*16+16) of the 32-wide key tile
//   ctx   : dims [half*32, half*32+32) of HD=64
// ---------------------------------------------------------------------------
__global__ __launch_bounds__(128) void attn_kernel(
    const float* __restrict__ mask, float* __restrict__ out)
{
    __shared__ float Qs[64][68];   // padded: float4-aligned, bank-spread
    __shared__ float Ks[32][64];
    __shared__ float Vs[32][64];
    __shared__ float Ps[64][33];
    __shared__ float mrow[64], lrow[64], arow[64];

    const int tid = threadIdx.x;
    const int qt = blockIdx.x;            // q tile
    const int bh = blockIdx.y;            // b * H + h
    const int b = bh >> 4;

    const float* Qg = g_q + (size_t)bh * Sn * HDn + (size_t)qt * 64 * HDn;
    const float* Kg = g_k + (size_t)bh * Sn * HDn;
    const float* Vg = g_v + (size_t)bh * Sn * HDn;

    const int r = tid & 63;
    const int half = tid >> 6;
    const int csBase = half * 16;   // score column base within key tile
    const int cdBase = half * 32;   // ctx dim base

    // Load Q tile: 64x64 floats = 1024 float4, 8 per thread.
#pragma unroll
    for (int i = 0; i < 8; i++) {
        int lin = tid + i * 128;
        int row = lin >> 4;
        int c4 = (lin & 15) << 2;
        *(float4*)&Qs[row][c4] = *(const float4*)(Qg + row * HDn + c4);
    }
    if (tid < 64) { mrow[tid] = -1e30f; lrow[tid] = 0.f; }

    float acc[32];
#pragma unroll
    for (int d = 0; d < 32; d++) acc[d] = 0.f;
    __syncthreads();

    for (int kt = 0; kt < Sn / 32; kt++) {
        // Load K,V tiles: 32x64 floats each = 512 float4, 4 per thread each.
#pragma unroll
        for (int i = 0; i < 4; i++) {
            int lin = tid + i * 128;
            int row = lin >> 4;
            int c4 = (lin & 15) << 2;
            *(float4*)&Ks[row][c4] = *(const float4*)(Kg + (size_t)kt * 32 * HDn + row * HDn + c4);
            *(float4*)&Vs[row][c4] = *(const float4*)(Vg + (size_t)kt * 32 * HDn + row * HDn + c4);
        }
        __syncthreads();

        // Scores: 16 columns per thread, dot over HD=64 via float4.
        float sreg[16];
#pragma unroll
        for (int j = 0; j < 16; j++) sreg[j] = 0.f;
#pragma unroll
        for (int k4 = 0; k4 < 16; k4++) {
            float4 q = *(const float4*)&Qs[r][k4 << 2];
#pragma unroll
            for (int j = 0; j < 16; j++) {
                float4 kv = *(const float4*)&Ks[csBase + j][k4 << 2];
                sreg[j] += q.x * kv.x + q.y * kv.y + q.z * kv.z + q.w * kv.w;
            }
        }
        const float scale = 0.125f;   // 1/sqrt(64)
#pragma unroll
        for (int j = 0; j < 16; j++) {
            int col = csBase + j;
            Ps[r][col] = sreg[j] * scale + mask[b * Sn + kt * 32 + col];
        }
        __syncthreads();

        // Online softmax update: one thread per row.
        if (tid < 64) {
            float mold = mrow[tid];
            float mt = mold;
#pragma unroll 8
            for (int j = 0; j < 32; j++) mt = fmaxf(mt, Ps[tid][j]);
            float a = __expf(mold - mt);
            float sum = 0.f;
#pragma unroll 8
            for (int j = 0; j < 32; j++) {
                float p = __expf(Ps[tid][j] - mt);
                Ps[tid][j] = p;
                sum += p;
            }
            lrow[tid] = lrow[tid] * a + sum;
            mrow[tid] = mt;
            arow[tid] = a;
        }
        __syncthreads();

        // Accumulate ctx: acc = acc*alpha + P @ V (32 dims per thread).
        float a = arow[r];
#pragma unroll
        for (int d = 0; d < 32; d++) acc[d] *= a;
#pragma unroll 4
        for (int j = 0; j < 32; j++) {
            float p = Ps[r][j];
#pragma unroll
            for (int d4 = 0; d4 < 8; d4++) {
                float4 v = *(const float4*)&Vs[j][cdBase + (d4 << 2)];
                acc[(d4 << 2) + 0] += p * v.x;
                acc[(d4 << 2) + 1] += p * v.y;
                acc[(d4 << 2) + 2] += p * v.z;
                acc[(d4 << 2) + 3] += p * v.w;
            }
        }
        __syncthreads();
    }

    // Final normalize + scatter to [B,S,D].
    const float inv = 1.f / lrow[r];
    const int qglob = qt * 64 + r;
    const int h = bh & 15;
    float* op = out + ((size_t)b * Sn + qglob) * Dn + h * HDn + cdBase;
#pragma unroll
    for (int d4 = 0; d4 < 8; d4++) {
        float4 v;
        v.x = acc[(d4 << 2) + 0] * inv;
        v.y = acc[(d4 << 2) + 1] * inv;
        v.z = acc[(d4 << 2) + 2] * inv;
        v.w = acc[(d4 << 2) + 3] * inv;
        *(float4*)(op + (d4 << 2)) = v;
    }
}

// ---------------------------------------------------------------------------
// Launch
// ---------------------------------------------------------------------------
extern "C" void kernel_launch(void* const* d_in, const int* in_sizes, int n_in,
                              void* d_out, int out_size)
{
    const float* hs   = (const float*)d_in[0];  // [B,S,D]
    const float* mask = (const float*)d_in[1];  // [B,1,1,S]
    const float* Wq   = (const float*)d_in[2];
    const float* bq   = (const float*)d_in[3];
    const float* Wk   = (const float*)d_in[4];
    const float* bk   = (const float*)d_in[5];
    const float* Wv   = (const float*)d_in[6];
    const float* bv   = (const float*)d_in[7];
    float* out = (float*)d_out;

    dim3 gemmGrid(Dn / 128, (Bn * Sn) / 128);   // (8, 64)
    qkv_gemm_kernel<<<gemmGrid, 256>>>(hs, Wq, bq, 0);
    qkv_gemm_kernel<<<gemmGrid, 256>>>(hs, Wk, bk, 1);
    qkv_gemm_kernel<<<gemmGrid, 256>>>(hs, Wv, bv, 2);

    dim3 attnGrid(Sn / 64, Bn * Hn);            // (16, 128)
    attn_kernel<<<attnGrid, 128>>>(mask, out);
}